// round 9
// baseline (speedup 1.0000x reference)
#include <cuda_runtime.h>
#include <cstdint>

#define SEQ    512
#define BATCH  512
#define IN_DIM 128
#define NQ     8
#define D_TOT  136   // IN_DIM + NQ

#define NBLK       148   // == wave-1 capacity, all co-resident
#define ZX_BLOCKS  116
#define ZX_ROWS    128   // rows per tile
#define N_TILES    ((SEQ * BATCH) / ZX_ROWS)   // 2048; 4 tiles per step

// Scratch: Zx[s][b][o], o = g*8 + q
__device__ float g_zx[(size_t)SEQ * BATCH * 32];
__device__ int g_step_done[SEQ];
__device__ int g_frontier;
__device__ int g_ticket;

typedef unsigned long long ull;

// --- packed fp32x2 ops (Blackwell; PTX-only) ---
__device__ __forceinline__ ull fma2(ull a, ull b, ull c) {
    ull d; asm("fma.rn.f32x2 %0, %1, %2, %3;" : "=l"(d) : "l"(a), "l"(b), "l"(c)); return d;
}
__device__ __forceinline__ ull mul2(ull a, ull b) {
    ull d; asm("mul.rn.f32x2 %0, %1, %2;" : "=l"(d) : "l"(a), "l"(b)); return d;
}
__device__ __forceinline__ ull add2(ull a, ull b) {
    ull d; asm("add.rn.f32x2 %0, %1, %2;" : "=l"(d) : "l"(a), "l"(b)); return d;
}
__device__ __forceinline__ ull pack2(float lo, float hi) {
    ull d; asm("mov.b64 %0, {%1, %2};" : "=l"(d) : "r"(__float_as_uint(lo)), "r"(__float_as_uint(hi))); return d;
}
__device__ __forceinline__ void unpack2(ull v, float& lo, float& hi) {
    unsigned a, b; asm("mov.b64 {%0, %1}, %2;" : "=r"(a), "=r"(b) : "l"(v));
    lo = __uint_as_float(a); hi = __uint_as_float(b);
}
__device__ __forceinline__ ull dup2(float x) {
    ull d; unsigned u = __float_as_uint(x);
    asm("mov.b64 %0, {%1, %1};" : "=l"(d) : "r"(u)); return d;
}
__device__ __forceinline__ float rcp_fast(float x) {
    float r; asm("rcp.approx.f32 %0, %1;" : "=f"(r) : "f"(x)); return r;
}
__device__ __forceinline__ int ld_acquire(const int* p) {
    int v; asm volatile("ld.acquire.gpu.b32 %0, [%1];" : "=r"(v) : "l"(p)); return v;
}

// ============================================================================
// Reset kernel: zero the sync state (runs before the fused kernel each call).
// ============================================================================
__global__ void reset_kernel() {
    int i = blockIdx.x * blockDim.x + threadIdx.x;
    if (i < SEQ) g_step_done[i] = 0;
    if (i == 0) { g_frontier = 0; g_ticket = 0; }
}

// ============================================================================
// Fused kernel. Blocks 0..115: zx producers. Blocks 116..147: rnn consumers.
// ============================================================================
__global__ void __launch_bounds__(128, 1) fused_kernel(
    const float* __restrict__ x, const float* __restrict__ W,
    const float* __restrict__ b, const float* __restrict__ qp,
    const float* __restrict__ h0, const float* __restrict__ c0,
    float* __restrict__ out)
{
    __shared__ ulonglong2 Ws[IN_DIM * 4];     // zx: outputs 0..15 of each d
    __shared__ ulonglong2 Ws_hi[IN_DIM * 4];  // zx: outputs 16..31 of each d
    __shared__ float bias[32];
    __shared__ float xs[ZX_ROWS * 33];        // zx: staged x / z (pad-33)
    __shared__ __align__(16) ulonglong2 Vbuf[4][2][32];  // rnn: per-warp exchange

    const unsigned FULL = 0xffffffffu;
    int tid = threadIdx.x;

    if (blockIdx.x < ZX_BLOCKS) {
        // ==================== ZX PRODUCER ====================
        float* WsF   = (float*)Ws;
        float* WsFhi = (float*)Ws_hi;
        for (int i = tid; i < IN_DIM * 32; i += 128) {
            int d = i >> 5, o = i & 31;
            float w = W[o * D_TOT + d];
            if (o < 16) WsF[d * 16 + o] = w;
            else        WsFhi[d * 16 + (o - 16)] = w;
        }
        if (tid < 32) bias[tid] = b[tid] + qp[tid];
        __syncthreads();

        __shared__ int s_tile;
        for (;;) {
            if (tid == 0) s_tile = atomicAdd(&g_ticket, 1);
            __syncthreads();
            int tile = s_tile;
            if (tile >= N_TILES) break;

            int rowbase = tile * ZX_ROWS;
            const float* xblk = x + (size_t)rowbase * IN_DIM;

            ull acc[16];
#pragma unroll
            for (int i = 0; i < 16; i++) acc[i] = 0ULL;

            for (int t = 0; t < IN_DIM / 32; t++) {
                __syncthreads();
#pragma unroll
                for (int k = 0; k < 8; k++) {
                    int idx = tid + k * 128;
                    int r = idx >> 3, d4 = idx & 7;
                    float4 v = *(const float4*)(xblk + (size_t)r * IN_DIM + t * 32 + d4 * 4);
                    float* dst = xs + r * 33 + d4 * 4;
                    dst[0] = v.x; dst[1] = v.y; dst[2] = v.z; dst[3] = v.w;
                }
                __syncthreads();

                const float* xr = xs + tid * 33;
#pragma unroll
                for (int dd = 0; dd < 32; dd++) {
                    int d = t * 32 + dd;
                    ull xv = dup2(xr[dd]);
                    const ulonglong2* wlo = Ws    + d * 4;
                    const ulonglong2* whi = Ws_hi + d * 4;
#pragma unroll
                    for (int j = 0; j < 4; j++) {
                        ulonglong2 wp = wlo[j];
                        acc[2 * j]     = fma2(xv, wp.x, acc[2 * j]);
                        acc[2 * j + 1] = fma2(xv, wp.y, acc[2 * j + 1]);
                    }
#pragma unroll
                    for (int j = 0; j < 4; j++) {
                        ulonglong2 wp = whi[j];
                        acc[8 + 2 * j]     = fma2(xv, wp.x, acc[8 + 2 * j]);
                        acc[8 + 2 * j + 1] = fma2(xv, wp.y, acc[8 + 2 * j + 1]);
                    }
                }
            }

            // stage z, coalesced store
            __syncthreads();
            {
                float* zrow = xs + tid * 33;
#pragma unroll
                for (int j = 0; j < 16; j++) {
                    float lo, hi; unpack2(acc[j], lo, hi);
                    zrow[2 * j]     = lo + bias[2 * j];
                    zrow[2 * j + 1] = hi + bias[2 * j + 1];
                }
            }
            __syncthreads();
#pragma unroll
            for (int k = 0; k < 8; k++) {
                int idx = tid + k * 128;
                int r = idx >> 3, d4 = idx & 7;
                const float* src = xs + r * 33 + d4 * 4;
                float4 v = make_float4(src[0], src[1], src[2], src[3]);
                *(float4*)(g_zx + (size_t)(rowbase + r) * 32 + d4 * 4) = v;
            }

            // publish: fence (each thread), barrier, one atomic
            __threadfence();
            __syncthreads();
            if (tid == 0) {
                int s = tile >> 2;
                int old = atomicAdd(&g_step_done[s], 1);
                if (old == 3) {
                    // advance frontier over consecutive completed steps
                    int f = ld_acquire(&g_frontier);
                    while (f < SEQ && ld_acquire(&g_step_done[f]) == 4) {
                        int prev = atomicCAS(&g_frontier, f, f + 1);
                        f = (prev == f) ? f + 1 : prev;
                    }
                }
            }
        }
        return;
    }

    // ==================== RNN CONSUMER ====================
    int lane = tid & 31;
    int warp = tid >> 5;
    int hf = lane & 1;
    int g  = (lane >> 1) & 3;
    int bl = lane >> 3;
    int bb = (blockIdx.x - ZX_BLOCKS) * 16 + warp * 4 + bl;   // batch 0..511
    bool owner = (g == 0);

    int sw  = bl * 8 + hf * 4 + (g ^ bl);
    int srb = bl * 8 + hf * 4;

    ull Wp[4][4];
#pragma unroll
    for (int r = 0; r < 4; r++) {
        const float* wr = W + (g * 8 + 4 * hf + r) * D_TOT + IN_DIM;
#pragma unroll
        for (int k = 0; k < 4; k++) {
            int qb = (k < 2) ? (4 * hf + 2 * k) : (4 * (1 - hf) + 2 * (k - 2));
            Wp[r][k] = pack2(wr[qb], wr[qb + 1]);
        }
    }

    ull hp[4];
    hp[0] = pack2(h0[bb * 8 + 4 * hf],           h0[bb * 8 + 4 * hf + 1]);
    hp[1] = pack2(h0[bb * 8 + 4 * hf + 2],       h0[bb * 8 + 4 * hf + 3]);
    hp[2] = pack2(h0[bb * 8 + 4 * (1 - hf)],     h0[bb * 8 + 4 * (1 - hf) + 1]);
    hp[3] = pack2(h0[bb * 8 + 4 * (1 - hf) + 2], h0[bb * 8 + 4 * (1 - hf) + 3]);

    float4 cv = *(const float4*)(c0 + bb * 8 + 4 * hf);
    ull Cp0 = pack2(cv.x, cv.y);
    ull Cp1 = pack2(cv.z, cv.w);

    bool is_g = (g == 2);
    ull P0  = dup2(is_g ? 105.0f : 26.25f);
    ull P1  = dup2(is_g ? 10.0f  : 0.625f);
    ull Q1  = dup2(is_g ? 45.0f  : 11.25f);
    ull Q2  = dup2(is_g ? 1.0f   : 0.0625f);
    ull ob2 = dup2(is_g ? 0.0f   : 0.5f);
    const ull C105 = dup2(105.0f), C945 = dup2(945.0f);
    const ull C15  = dup2(15.0f),  C420 = dup2(420.0f);

    const float4* zp = (const float4*)g_zx + ((size_t)bb * 8 + g * 2 + hf);
    const size_t Z4STRIDE = (size_t)BATCH * 8;

    // wait until steps 0..3 are produced, then preload
    int hw = ld_acquire(&g_frontier);
    while (hw < 4) hw = ld_acquire(&g_frontier);

    float4 zb[4];
#pragma unroll
    for (int u = 0; u < 4; u++) zb[u] = zp[(size_t)u * Z4STRIDE];

    float4* op4 = (float4*)(out + (size_t)bb * 8 + 4 * hf);
    const size_t O4STRIDE = (size_t)BATCH * 2;

    ull H0 = 0ULL, H1 = 0ULL;

    for (int s = 0; s < SEQ; s += 4) {
#pragma unroll
        for (int u = 0; u < 4; u++) {
            int sp = s + u + 4; sp = sp < SEQ ? sp : SEQ - 1;
            // ensure step sp is produced (off critical path: 4-step slack)
            if (hw <= sp) {
                hw = ld_acquire(&g_frontier);
                while (hw <= sp) hw = ld_acquire(&g_frontier);
            }
            float4 zn = zp[(size_t)sp * Z4STRIDE];

            // dot per row
            ull ac0 = mul2(hp[0], Wp[0][0]);
            ull ac1 = mul2(hp[0], Wp[1][0]);
            ull ac2 = mul2(hp[0], Wp[2][0]);
            ull ac3 = mul2(hp[0], Wp[3][0]);
#pragma unroll
            for (int k = 1; k < 4; k++) {
                ac0 = fma2(hp[k], Wp[0][k], ac0);
                ac1 = fma2(hp[k], Wp[1][k], ac1);
                ac2 = fma2(hp[k], Wp[2][k], ac2);
                ac3 = fma2(hp[k], Wp[3][k], ac3);
            }
            float l0, l1, l2, l3, r0, r1, r2, r3;
            unpack2(ac0, l0, r0); unpack2(ac1, l1, r1);
            unpack2(ac2, l2, r2); unpack2(ac3, l3, r3);
            float a0 = __cosf(zb[u].x + l0 + r0);
            float a1 = __cosf(zb[u].y + l1 + r1);
            float a2 = __cosf(zb[u].z + l2 + r2);
            float a3 = __cosf(zb[u].w + l3 + r3);

            // local cumprod of 4 + cross-half prefix
            float k1 = a0 * a1;
            float t23 = a2 * a3;
            float k2 = k1 * a2;
            float k3 = k1 * t23;
            float T = __shfl_xor_sync(FULL, k3, 1);
            ull M = dup2(hf ? T : 1.0f);
            ull X0 = mul2(M, pack2(a0, k1));
            ull X1 = mul2(M, pack2(k2, k3));

            // gate rational
            ull T0 = mul2(X0, X0), T1 = mul2(X1, X1);
            ull N0 = mul2(X0, fma2(P1, T0, P0));
            ull N1 = mul2(X1, fma2(P1, T1, P0));
            ull B0 = fma2(fma2(Q2, T0, Q1), T0, C105);
            ull B1 = fma2(fma2(Q2, T1, Q1), T1, C105);
            float d0, d1, d2, d3, n0, n1, n2, n3;
            unpack2(B0, d0, d1); unpack2(B1, d2, d3);
            unpack2(N0, n0, n1); unpack2(N1, n2, n3);
            float inv0 = rcp_fast(d0 * d1);
            float inv1 = rcp_fast(d2 * d3);
            ull V0 = fma2(pack2(n0 * d1, n1 * d0), dup2(inv0), ob2);
            ull V1 = fma2(pack2(n2 * d3, n3 * d2), dup2(inv1), ob2);

            // smem gate exchange (per-warp buffer, double-buffered)
            ulonglong2* buf = Vbuf[warp][u & 1];
            ulonglong2 vpk; vpk.x = V0; vpk.y = V1;
            buf[sw] = vpk;
            __syncwarp(FULL);
            ulonglong2 Fv = buf[srb + (0 ^ bl)];
            ulonglong2 Iv = buf[srb + (1 ^ bl)];
            ulonglong2 Gv = buf[srb + (2 ^ bl)];
            ulonglong2 Ov = buf[srb + (3 ^ bl)];

            // cell update + cell tanh
            Cp0 = fma2(Fv.x, Cp0, mul2(Iv.x, Gv.x));
            Cp1 = fma2(Fv.y, Cp1, mul2(Iv.y, Gv.y));
            ull TC0 = mul2(Cp0, Cp0), TC1 = mul2(Cp1, Cp1);
            ull NC0 = mul2(Cp0, fma2(add2(TC0, C105), TC0, C945));
            ull NC1 = mul2(Cp1, fma2(add2(TC1, C105), TC1, C945));
            ull BC0 = fma2(fma2(C15, TC0, C420), TC0, C945);
            ull BC1 = fma2(fma2(C15, TC1, C420), TC1, C945);
            float e0, e1, e2, e3, m0, m1, m2, m3;
            unpack2(BC0, e0, e1); unpack2(BC1, e2, e3);
            unpack2(NC0, m0, m1); unpack2(NC1, m2, m3);
            float iv0 = rcp_fast(e0 * e1);
            float iv1 = rcp_fast(e2 * e3);
            ull TH0 = mul2(pack2(m0 * e1, m1 * e0), dup2(iv0));
            ull TH1 = mul2(pack2(m2 * e3, m3 * e2), dup2(iv1));

            H0 = mul2(Ov.x, TH0);
            H1 = mul2(Ov.y, TH1);

            // half exchange
            ull Hx0 = __shfl_xor_sync(FULL, H0, 1);
            ull Hx1 = __shfl_xor_sync(FULL, H1, 1);
            hp[0] = H0; hp[1] = H1; hp[2] = Hx0; hp[3] = Hx1;

            if (owner) {
                float x0, x1, x2, x3;
                unpack2(H0, x0, x1); unpack2(H1, x2, x3);
                *op4 = make_float4(x0, x1, x2, x3);
            }
            op4 += O4STRIDE;

            zb[u] = zn;
        }
    }

    size_t base = (size_t)SEQ * BATCH * 8;
    if (owner) {
        float x0, x1, x2, x3, y0, y1, y2, y3;
        unpack2(H0, x0, x1); unpack2(H1, x2, x3);
        unpack2(Cp0, y0, y1); unpack2(Cp1, y2, y3);
        *(float4*)(out + base + (size_t)bb * 8 + 4 * hf) = make_float4(x0, x1, x2, x3);
        *(float4*)(out + base + BATCH * 8 + (size_t)bb * 8 + 4 * hf) = make_float4(y0, y1, y2, y3);
    }
}

extern "C" void kernel_launch(void* const* d_in, const int* in_sizes, int n_in,
                              void* d_out, int out_size) {
    const float* x  = (const float*)d_in[0];   // inputs (512,512,128)
    const float* h0 = (const float*)d_in[1];   // (512,8)
    const float* c0 = (const float*)d_in[2];   // (512,8)
    const float* W  = (const float*)d_in[3];   // (4,8,136)
    const float* b  = (const float*)d_in[4];   // (4,8)
    const float* qp = (const float*)d_in[5];   // (4,8)
    float* out = (float*)d_out;

    reset_kernel<<<2, 256>>>();
    fused_kernel<<<NBLK, 128>>>(x, W, b, qp, h0, c0, out);
}